// round 14
// baseline (speedup 1.0000x reference)
#include <cuda_runtime.h>
#include <cuda_bf16.h>
#include <cstdint>

// ---- problem constants ----
#define Bq   4
#define Tq   1024
#define Eq   512
#define Hq   8
#define HDq  64
#define NBq  5
#define VOC  32000
#define MROWS (Bq*Tq)          // 4096

// ---- scratch (device globals; no allocations allowed) ----
__device__ float g_h1 [MROWS*Eq];
__device__ float g_h2 [MROWS*Eq];
__device__ float g_kq [MROWS*1024];     // fused K|Q output
__device__ float g_mha[MROWS*Eq];
// activation hi/lo splits (bf16)
__device__ __nv_bfloat16 g_h1hi[MROWS*Eq], g_h1lo[MROWS*Eq];
__device__ __nv_bfloat16 g_hnhi[MROWS*Eq], g_hnlo[MROWS*Eq];
// weight hi/lo splits, transposed to [N][K=512] row-major
__device__ __nv_bfloat16 g_wkqhi[NBq*1024*Eq], g_wkqlo[NBq*1024*Eq];   // K|Q concat
__device__ __nv_bfloat16 g_wrhi[NBq*Eq*Eq], g_wrlo[NBq*Eq*Eq];
__device__ __nv_bfloat16 g_wmhi[NBq*Eq*Eq], g_wmlo[NBq*Eq*Eq];
__device__ __nv_bfloat16 g_pjhi[(size_t)Eq*VOC], g_pjlo[(size_t)Eq*VOC];

// ============================================================
// helpers
// ============================================================
__device__ __forceinline__ uint32_t smem_u32(const void* p) {
    uint32_t a;
    asm("{ .reg .u64 t; cvta.to.shared.u64 t, %1; cvt.u32.u64 %0, t; }"
        : "=r"(a) : "l"(p));
    return a;
}
__device__ __forceinline__ void ldsm4(uint32_t* r, uint32_t addr) {
    asm volatile("ldmatrix.sync.aligned.m8n8.x4.shared.b16 {%0,%1,%2,%3}, [%4];"
                 : "=r"(r[0]), "=r"(r[1]), "=r"(r[2]), "=r"(r[3]) : "r"(addr));
}
__device__ __forceinline__ void mma16816(float* c, const uint32_t* a, const uint32_t* b) {
    asm volatile(
        "mma.sync.aligned.m16n8k16.row.col.f32.bf16.bf16.f32 "
        "{%0,%1,%2,%3}, {%4,%5,%6,%7}, {%8,%9}, {%0,%1,%2,%3};"
        : "+f"(c[0]), "+f"(c[1]), "+f"(c[2]), "+f"(c[3])
        : "r"(a[0]), "r"(a[1]), "r"(a[2]), "r"(a[3]), "r"(b[0]), "r"(b[1]));
}
#define CPASYNC(dst, src) \
    asm volatile("cp.async.cg.shared.global [%0], [%1], 16;" :: "r"(dst), "l"(src))
#define CPCOMMIT() asm volatile("cp.async.commit_group;" ::: "memory")
#define CPWAIT1()  asm volatile("cp.async.wait_group 1;" ::: "memory")
#define CPWAIT0()  asm volatile("cp.async.wait_group 0;" ::: "memory")

__device__ __forceinline__ uint32_t pack_hi2(float x, float y) {
    __nv_bfloat16 hx = __float2bfloat16(x), hy = __float2bfloat16(y);
    return (uint32_t)__bfloat16_as_ushort(hx) | ((uint32_t)__bfloat16_as_ushort(hy) << 16);
}
__device__ __forceinline__ uint32_t pack_lo2(float x, float y) {
    __nv_bfloat16 hx = __float2bfloat16(x), hy = __float2bfloat16(y);
    __nv_bfloat16 lx = __float2bfloat16(x - __bfloat162float(hx));
    __nv_bfloat16 ly = __float2bfloat16(y - __bfloat162float(hy));
    return (uint32_t)__bfloat16_as_ushort(lx) | ((uint32_t)__bfloat16_as_ushort(ly) << 16);
}

// ============================================================
// prep_all: ALL weight prep in ONE launch (32x32 transpose-split tiles)
// ============================================================
__global__ __launch_bounds__(256) void prep_all(
    const float* __restrict__ Wk, const float* __restrict__ Wq,
    const float* __restrict__ Wres, const float* __restrict__ mlpW,
    const float* __restrict__ projW,
    __nv_bfloat16* __restrict__ kqhi, __nv_bfloat16* __restrict__ kqlo,
    __nv_bfloat16* __restrict__ rhi,  __nv_bfloat16* __restrict__ rlo,
    __nv_bfloat16* __restrict__ mhi,  __nv_bfloat16* __restrict__ mlo,
    __nv_bfloat16* __restrict__ phi,  __nv_bfloat16* __restrict__ plo)
{
    __shared__ float t[32][33];
    int j = blockIdx.x;
    const float* src; int rs; size_t ibase, obase;
    __nv_bfloat16 *oh, *ol;

    if (j < 2560) {                       // Wk / Wq: [nbh][e][hd] -> [nb][1024][512]
        int q = (j >= 1280);
        int u = j - q * 1280;
        int nbh = u >> 5, tt = u & 31;
        int et = tt & 15, ht = tt >> 4;
        int nb = nbh >> 3, h = nbh & 7;
        int e0 = et * 32, hd0 = ht * 32;
        src   = q ? Wq : Wk;
        rs    = HDq;
        ibase = ((size_t)nbh * Eq + e0) * HDq + hd0;
        obase = ((size_t)nb * 1024 + q * 512 + h * HDq + hd0) * 512 + e0;
        oh = kqhi; ol = kqlo;
    } else if (j < 5120) {                // Wres / mlpW: [nb][k][n] -> [nb][512][512]
        int q = (j >= 3840);
        int u = j - 2560 - q * 1280;
        int nb = u >> 8, tt = u & 255;
        int nt = tt & 15, kt = tt >> 4;
        int n0 = nt * 32, k0 = kt * 32;
        src   = q ? mlpW : Wres;
        rs    = Eq;
        ibase = ((size_t)nb * Eq + k0) * Eq + n0;
        obase = ((size_t)nb * Eq + n0) * Eq + k0;
        oh = q ? mhi : rhi; ol = q ? mlo : rlo;
    } else {                              // projW [512][VOC] -> [VOC][512]
        int u = j - 5120;
        int nt = u % 1000, kt = u / 1000;
        int n0 = nt * 32, k0 = kt * 32;
        src   = projW;
        rs    = VOC;
        ibase = (size_t)k0 * VOC + n0;
        obase = (size_t)n0 * 512 + k0;
        oh = phi; ol = plo;
    }

    int lw = threadIdx.x >> 5, lc = threadIdx.x & 31;
    #pragma unroll
    for (int i = 0; i < 4; i++) {
        int r = lw + i * 8;
        t[r][lc] = src[ibase + (size_t)r * rs + lc];
    }
    __syncthreads();
    #pragma unroll
    for (int i = 0; i < 4; i++) {
        int c = lw + i * 8;
        float v = t[lc][c];
        __nv_bfloat16 h = __float2bfloat16(v);
        __nv_bfloat16 l = __float2bfloat16(v - __bfloat162float(h));
        size_t o = obase + (size_t)c * 512 + lc;
        oh[o] = h; ol[o] = l;
    }
}

// ============================================================
// embedding: h = tok_emb[x] + pos_emb ; also write hi/lo split
// ============================================================
__global__ void embed_kernel(const int* __restrict__ x,
                             const float* __restrict__ tok,
                             const float* __restrict__ pos,
                             float* __restrict__ h,
                             __nv_bfloat16* __restrict__ ohi,
                             __nv_bfloat16* __restrict__ olo)
{
    int row = blockIdx.x;
    int t   = row & (Tq - 1);
    int idx = x[row];
    int tid = threadIdx.x;
    float4 a = ((const float4*)(tok + (size_t)idx * Eq))[tid];
    float4 p = ((const float4*)(pos + (size_t)t   * Eq))[tid];
    float4 o; o.x = a.x+p.x; o.y = a.y+p.y; o.z = a.z+p.z; o.w = a.w+p.w;
    ((float4*)(h + (size_t)row * Eq))[tid] = o;
    size_t e = (size_t)row * Eq + tid * 4;
    *(uint2*)(ohi + e) = make_uint2(pack_hi2(o.x, o.y), pack_hi2(o.z, o.w));
    *(uint2*)(olo + e) = make_uint2(pack_lo2(o.x, o.y), pack_lo2(o.z, o.w));
}

// ============================================================
// layernorm -> hi/lo bf16 split
// ============================================================
__global__ void ln_split_kernel(const float* __restrict__ in,
                                const float* __restrict__ g,
                                const float* __restrict__ b,
                                __nv_bfloat16* __restrict__ ohi,
                                __nv_bfloat16* __restrict__ olo)
{
    int row = blockIdx.x, tid = threadIdx.x;
    float4 v = ((const float4*)(in + (size_t)row * Eq))[tid];
    float s  = v.x + v.y + v.z + v.w;
    float sq = v.x*v.x + v.y*v.y + v.z*v.z + v.w*v.w;
    #pragma unroll
    for (int o = 16; o; o >>= 1) {
        s  += __shfl_xor_sync(0xffffffffu, s,  o);
        sq += __shfl_xor_sync(0xffffffffu, sq, o);
    }
    __shared__ float sm1[4], sm2[4];
    int wid = tid >> 5, lane = tid & 31;
    if (lane == 0) { sm1[wid] = s; sm2[wid] = sq; }
    __syncthreads();
    s  = sm1[0] + sm1[1] + sm1[2] + sm1[3];
    sq = sm2[0] + sm2[1] + sm2[2] + sm2[3];
    float mu   = s * (1.0f / Eq);
    float var  = sq * (1.0f / Eq) - mu * mu;
    float rstd = rsqrtf(var + 1e-5f);
    float4 gv = ((const float4*)g)[tid];
    float4 bv = ((const float4*)b)[tid];
    float4 o;
    o.x = (v.x - mu) * rstd * gv.x + bv.x;
    o.y = (v.y - mu) * rstd * gv.y + bv.y;
    o.z = (v.z - mu) * rstd * gv.z + bv.z;
    o.w = (v.w - mu) * rstd * gv.w + bv.w;
    size_t e = (size_t)row * Eq + tid * 4;
    *(uint2*)(ohi + e) = make_uint2(pack_hi2(o.x, o.y), pack_hi2(o.z, o.w));
    *(uint2*)(olo + e) = make_uint2(pack_lo2(o.x, o.y), pack_lo2(o.z, o.w));
}

// ============================================================
// bf16x3 HMMA GEMM v3: C[M,N] = A[M,512] @ W[512,N]
// acc += Ahi*Bhi + Ahi*Blo + Alo*Bhi  (fp32 accumulate)
// 128x64x32 tile, 256 thr = 8 warps (4m x 2n), warp 32x32.
// 2-stage cp.async, XOR-swizzled 64B rows, 48KB smem.
// ALL fragments for both kk sub-steps are LDSM'd up front each
// stage so the 48 MMAs overlap the tail LDSM latency
// (needs ~116 regs -> __launch_bounds__(256,2), 2 CTAs/SM).
// ============================================================
#define A_HI 0
#define A_LO 8192
#define B_HI 16384
#define B_LO 20480
#define STAGEB 24576
#define SMEMB  (2 * STAGEB)             // 49152

template<bool BIAS, bool RELU, bool RESID, bool OSPLIT>
__global__ __launch_bounds__(256, 2) void hgemm(
    const __nv_bfloat16* __restrict__ Ahi, const __nv_bfloat16* __restrict__ Alo,
    const __nv_bfloat16* __restrict__ Bhi, const __nv_bfloat16* __restrict__ Blo,
    const float* __restrict__ bias, const float* __restrict__ resid,
    float* __restrict__ C,
    __nv_bfloat16* __restrict__ Ohi, __nv_bfloat16* __restrict__ Olo,
    int N)
{
    extern __shared__ char dsm[];
    const uint32_t sb = smem_u32(dsm);
    const int tid = threadIdx.x;
    const int wid = tid >> 5, lane = tid & 31;
    const int wm = wid & 3, wn = wid >> 2;
    const int m0 = blockIdx.x * 128, n0 = blockIdx.y * 64;

    // ldmatrix per-lane smem offsets (swizzled)
    uint32_t aOff[2], bOff[2];
    {
        int ml = lane >> 3, r8 = lane & 7;
        int ar  = (ml & 1) * 8 + r8;
        int ac2 = ((ml >> 1) * 8) * 2;            // col bytes: 0 or 16
        #pragma unroll
        for (int mi = 0; mi < 2; mi++) {
            int row = wm * 32 + mi * 16 + ar;
            aOff[mi] = (uint32_t)(row * 64 + (ac2 ^ (((row >> 1) & 3) << 4)));
        }
        int br  = (ml >> 1) * 8 + r8;
        int bc2 = ((ml & 1) * 8) * 2;
        #pragma unroll
        for (int j = 0; j < 2; j++) {
            int row = wn * 32 + j * 16 + br;
            bOff[j] = (uint32_t)(row * 64 + (bc2 ^ (((row >> 1) & 3) << 4)));
        }
    }

    auto loadStage = [&](int s) {
        uint32_t base = sb + (s & 1) * STAGEB;
        #pragma unroll
        for (int i = 0; i < 2; i++) {             // A: 512 chunks (hi+lo pairs)
            int idx = tid + i * 256;
            int row = idx >> 2, ch = idx & 3;
            uint32_t doff = (uint32_t)(row * 64 + ((ch ^ ((row >> 1) & 3)) << 4));
            size_t ga = (size_t)(m0 + row) * 512 + s * 32 + ch * 8;
            CPASYNC(base + A_HI + doff, Ahi + ga);
            CPASYNC(base + A_LO + doff, Alo + ga);
        }
        {                                          // B: 256 chunks (hi+lo pairs)
            int row = tid >> 2, ch = tid & 3;
            uint32_t doff = (uint32_t)(row * 64 + ((ch ^ ((row >> 1) & 3)) << 4));
            size_t gb = (size_t)(n0 + row) * 512 + s * 32 + ch * 8;
            CPASYNC(base + B_HI + doff, Bhi + gb);
            CPASYNC(base + B_LO + doff, Blo + gb);
        }
    };

    float acc[2][4][4];
    #pragma unroll
    for (int i = 0; i < 2; i++)
        #pragma unroll
        for (int j = 0; j < 4; j++)
            #pragma unroll
            for (int q = 0; q < 4; q++) acc[i][j][q] = 0.0f;

    loadStage(0); CPCOMMIT();

    for (int s = 0; s < 16; s++) {
        if (s + 1 < 16) { loadStage(s + 1); CPCOMMIT(); CPWAIT1(); }
        else            { CPWAIT0(); }
        __syncthreads();                 // stage s visible to all warps
        uint32_t base = sb + (s & 1) * STAGEB;

        // --- LDSM everything for BOTH kk sub-steps up front ---
        uint32_t ah[2][8], al[2][8], bh[2][8], bl[2][8];
        #pragma unroll
        for (int kk = 0; kk < 2; kk++) {
            uint32_t kx = (uint32_t)(kk << 5);    // +32B col == XOR (disjoint bit)
            #pragma unroll
            for (int mi = 0; mi < 2; mi++) {
                ldsm4(ah[kk] + mi * 4, base + A_HI + (aOff[mi] ^ kx));
                ldsm4(al[kk] + mi * 4, base + A_LO + (aOff[mi] ^ kx));
            }
            #pragma unroll
            for (int j = 0; j < 2; j++) {
                ldsm4(bh[kk] + j * 4, base + B_HI + (bOff[j] ^ kx));
                ldsm4(bl[kk] + j * 4, base + B_LO + (bOff[j] ^ kx));
            }
        }
        // --- 48 MMAs overlap the tail LDSMs ---
        #pragma unroll
        for (int kk = 0; kk < 2; kk++)
            #pragma unroll
            for (int mi = 0; mi < 2; mi++)
                #pragma unroll
                for (int ni = 0; ni < 4; ni++) {
                    mma16816(acc[mi][ni], ah[kk] + mi * 4, bh[kk] + ni * 2);
                    mma16816(acc[mi][ni], ah[kk] + mi * 4, bl[kk] + ni * 2);
                    mma16816(acc[mi][ni], al[kk] + mi * 4, bh[kk] + ni * 2);
                }
        __syncthreads();                 // all warps done with stage s buffer
    }

    // epilogue
    const int r  = lane >> 2;
    const int cp = (lane & 3) * 2;
    #pragma unroll
    for (int mi = 0; mi < 2; mi++) {
        #pragma unroll
        for (int ni = 0; ni < 4; ni++) {
            int col  = n0 + wn * 32 + ni * 8 + cp;
            int row0 = m0 + wm * 32 + mi * 16 + r;
            #pragma unroll
            for (int hh = 0; hh < 2; hh++) {
                int row = row0 + hh * 8;
                float v0 = acc[mi][ni][hh * 2];
                float v1 = acc[mi][ni][hh * 2 + 1];
                if (BIAS) { v0 += bias[col]; v1 += bias[col + 1]; }
                if (RELU) { v0 = fmaxf(v0, 0.0f); v1 = fmaxf(v1, 0.0f); }
                if (RESID) {
                    float2 rr = *(const float2*)(resid + (size_t)row * N + col);
                    v0 += rr.x; v1 += rr.y;
                }
                *(float2*)(C + (size_t)row * N + col) = make_float2(v0, v1);
                if (OSPLIT) {
                    *(uint32_t*)(Ohi + (size_t)row * N + col) = pack_hi2(v0, v1);
                    *(uint32_t*)(Olo + (size_t)row * N + col) = pack_lo2(v0, v1);
                }
            }
        }
    }
}

// ============================================================
// fused causal attention (quirks: scores = k[t]@q[s], v == q,
// scale = E^-0.5). KQ packed [M][1024] (K 0..511, Q 512..1023).
// No-max softmax; lane-parallel scoring; k in registers.
// grid (T/8, B*H), 8 warps; warp = query row t.
// ============================================================
__global__ __launch_bounds__(256) void attn_kernel(
    const float* __restrict__ KQ, float* __restrict__ O)
{
    __shared__ float2 qs2[128][34];               // stride 68 words: conflict-free
    int bh = blockIdx.y;
    int b = bh >> 3, h = bh & 7;
    int wid = threadIdx.x >> 5, lane = threadIdx.x & 31;
    int t = blockIdx.x * 8 + wid;
    const float scale = 0.044194173824159216f;    // 512^-0.5

    float kreg[64];
    {
        const float* kp = KQ + ((size_t)(b * Tq + t)) * 1024 + h * HDq;
        #pragma unroll
        for (int i = 0; i < 16; i++) {
            float4 v = *(const float4*)(kp + i * 4);
            kreg[i*4+0] = v.x * scale; kreg[i*4+1] = v.y * scale;
            kreg[i*4+2] = v.z * scale; kreg[i*4+3] = v.w * scale;
        }
    }

    float a0e = 0.f, a0o = 0.f, a1e = 0.f, a1o = 0.f, l = 0.f;
    int tmax = blockIdx.x * 8 + 7;

    for (int s0 = 0; s0 <= tmax; s0 += 128) {
        #pragma unroll
        for (int it = 0; it < 4; it++) {
            int idx = it * 256 + threadIdx.x;
            int row = idx >> 3, jj = idx & 7, c = jj * 4;
            const float* qp = KQ + (size_t)(b * Tq + s0 + row) * 1024 + 512 + h * HDq;
            float4 lo = *(const float4*)(qp + c);
            float4 hi = *(const float4*)(qp + c + 32);
            *(float4*)&qs2[row][c]     = make_float4(lo.x, hi.x, lo.y, hi.y);
            *(float4*)&qs2[row][c + 2] = make_float4(lo.z, hi.z, lo.w, hi.w);
        }
        __syncthreads();

        int send = min(127, t - s0);
        int nch = (send >> 5) + 1;
        for (int c = 0; c < nch; c++) {
            int sb32 = c * 32;
            int srow = sb32 + lane;
            const float2* qr = qs2[srow];
            float p0 = 0.f, p1 = 0.f, p2 = 0.f, p3 = 0.f;
            #pragma unroll
            for (int d2 = 0; d2 < 32; d2 += 4) {
                float4 A = *(const float4*)&qr[d2];
                float4 Bv = *(const float4*)&qr[d2 + 2];
                p0 = fmaf(kreg[d2],      A.x,  p0);
                p1 = fmaf(kreg[d2 + 32], A.y,  p1);
                p2 = fmaf(kreg[d2 + 1],  A.z,  p2);
                p3 = fmaf(kreg[d2 + 33], A.w,  p3);
                p0 = fmaf(kreg[d2 + 2],  Bv.x, p0);
                p1 = fmaf(kreg[d2 + 34], Bv.y, p1);
                p2 = fmaf(kreg[d2 + 3],  Bv.z, p2);
                p3 = fmaf(kreg[d2 + 35], Bv.w, p3);
            }
            float p = (p0 + p1) + (p2 + p3);
            float w = (srow <= send) ? __expf(p) : 0.0f;
            l += w;
            #pragma unroll
            for (int s2 = 0; s2 < 32; s2 += 2) {
                float w0 = __shfl_sync(0xffffffffu, w, s2);
                float w1 = __shfl_sync(0xffffffffu, w, s2 + 1);
                float2 q0 = qs2[sb32 + s2][lane];
                float2 q1 = qs2[sb32 + s2 + 1][lane];
                a0e = fmaf(w0, q0.x, a0e); a1e = fmaf(w0, q0.y, a1e);
                a0o = fmaf(w1, q1.x, a0o); a1o = fmaf(w1, q1.y, a1o);
            }
        }
        __syncthreads();
    }

    float lt = l;
    #pragma unroll
    for (int o = 16; o; o >>= 1)
        lt += __shfl_xor_sync(0xffffffffu, lt, o);
    float inv = 1.0f / lt;
    size_t obase = ((size_t)(b * Tq + t)) * Eq + h * HDq;
    O[obase + lane]      = (a0e + a0o) * inv;
    O[obase + lane + 32] = (a1e + a1o) * inv;
}

// ============================================================
// launch
// ============================================================
extern "C" void kernel_launch(void* const* d_in, const int* in_sizes, int n_in,
                              void* d_out, int out_size)
{
    const int*   x     = (const int*)  d_in[0];
    const float* tok   = (const float*)d_in[1];
    const float* pos   = (const float*)d_in[2];
    const float* Wk    = (const float*)d_in[3];
    const float* Wq    = (const float*)d_in[4];
    const float* Wres  = (const float*)d_in[5];
    const float* ln1g  = (const float*)d_in[6];
    const float* ln1b  = (const float*)d_in[7];
    const float* mlpW  = (const float*)d_in[8];
    const float* mlpb  = (const float*)d_in[9];
    const float* ln2g  = (const float*)d_in[10];
    const float* ln2b  = (const float*)d_in[11];
    const float* lnfg  = (const float*)d_in[12];
    const float* lnfb  = (const float*)d_in[13];
    const float* projW = (const float*)d_in[14];
    const float* projb = (const float*)d_in[15];
    float* out = (float*)d_out;

    float *h1, *h2, *kq, *mha;
    __nv_bfloat16 *h1hi, *h1lo, *hnhi, *hnlo;
    __nv_bfloat16 *wkqhi, *wkqlo, *wrhi, *wrlo, *wmhi, *wmlo, *pjhi, *pjlo;
    cudaGetSymbolAddress((void**)&h1,  g_h1);
    cudaGetSymbolAddress((void**)&h2,  g_h2);
    cudaGetSymbolAddress((void**)&kq,  g_kq);
    cudaGetSymbolAddress((void**)&mha, g_mha);
    cudaGetSymbolAddress((void**)&h1hi, g_h1hi);
    cudaGetSymbolAddress((void**)&h1lo, g_h1lo);
    cudaGetSymbolAddress((void**)&hnhi, g_hnhi);
    cudaGetSymbolAddress((void**)&hnlo, g_hnlo);
    cudaGetSymbolAddress((void**)&wkqhi, g_wkqhi);
    cudaGetSymbolAddress((void**)&wkqlo, g_wkqlo);
    cudaGetSymbolAddress((void**)&wrhi, g_wrhi);
    cudaGetSymbolAddress((void**)&wrlo, g_wrlo);
    cudaGetSymbolAddress((void**)&wmhi, g_wmhi);
    cudaGetSymbolAddress((void**)&wmlo, g_wmlo);
    cudaGetSymbolAddress((void**)&pjhi, g_pjhi);
    cudaGetSymbolAddress((void**)&pjlo, g_pjlo);

    cudaFuncSetAttribute(hgemm<false,false,false,false>, cudaFuncAttributeMaxDynamicSharedMemorySize, SMEMB);
    cudaFuncSetAttribute(hgemm<false,false,true,false>,  cudaFuncAttributeMaxDynamicSharedMemorySize, SMEMB);
    cudaFuncSetAttribute(hgemm<true,true,true,true>,     cudaFuncAttributeMaxDynamicSharedMemorySize, SMEMB);
    cudaFuncSetAttribute(hgemm<true,false,false,false>,  cudaFuncAttributeMaxDynamicSharedMemorySize, SMEMB);

    prep_all<<<21120, 256>>>(Wk, Wq, Wres, mlpW, projW,
                             wkqhi, wkqlo, wrhi, wrlo, wmhi, wmlo, pjhi, pjlo);
    embed_kernel<<<MROWS, 128>>>(x, tok, pos, h1, h1hi, h1lo);

    dim3 gkq(MROWS / 128, 1024 / 64);            // 32 x 16 = 512 CTAs
    dim3 ge (MROWS / 128, Eq / 64);              // 32 x 8  = 256 CTAs
    for (int i = 0; i < NBq; i++) {
        const size_t wo   = (size_t)i * Eq * Eq;
        const size_t wokq = (size_t)i * 1024 * Eq;
        ln_split_kernel<<<MROWS, 128>>>(h1, ln1g + i * Eq, ln1b + i * Eq, hnhi, hnlo);
        hgemm<false,false,false,false><<<gkq, 256, SMEMB>>>(
            hnhi, hnlo, wkqhi + wokq, wkqlo + wokq, nullptr, nullptr, kq, nullptr, nullptr, 1024);
        attn_kernel<<<dim3(Tq / 8, Bq * Hq), 256>>>(kq, mha);
        hgemm<false,false,true,false><<<ge, 256, SMEMB>>>(
            h1hi, h1lo, wrhi + wo, wrlo + wo, nullptr, mha, h2, nullptr, nullptr, Eq);
        ln_split_kernel<<<MROWS, 128>>>(h2, ln2g + i * Eq, ln2b + i * Eq, hnhi, hnlo);
        hgemm<true,true,true,true><<<ge, 256, SMEMB>>>(
            hnhi, hnlo, wmhi + wo, wmlo + wo, mlpb + i * Eq, h2, h1, h1hi, h1lo, Eq);
    }

    ln_split_kernel<<<MROWS, 128>>>(h1, lnfg, lnfb, hnhi, hnlo);
    hgemm<true,false,false,false><<<dim3(MROWS / 128, VOC / 64), 256, SMEMB>>>(
        hnhi, hnlo, pjhi, pjlo, projb, nullptr, out, nullptr, nullptr, VOC);
}

// round 15
// speedup vs baseline: 1.1057x; 1.1057x over previous
#include <cuda_runtime.h>
#include <cuda_bf16.h>
#include <cuda_fp16.h>
#include <cstdint>

// ---- problem constants ----
#define Bq   4
#define Tq   1024
#define Eq   512
#define Hq   8
#define HDq  64
#define NBq  5
#define VOC  32000
#define MROWS (Bq*Tq)          // 4096

// ---- scratch (device globals; no allocations allowed) ----
__device__ float g_h1 [MROWS*Eq];
__device__ float g_h2 [MROWS*Eq];
__device__ float g_kq [MROWS*1024];     // fused K|Q output
__device__ float g_mha[MROWS*Eq];
// activation hi/lo splits (bf16 for blocks; final LN reuses as fp16)
__device__ __nv_bfloat16 g_h1hi[MROWS*Eq], g_h1lo[MROWS*Eq];
__device__ __nv_bfloat16 g_hnhi[MROWS*Eq], g_hnlo[MROWS*Eq];
// weight splits, transposed to [N][K=512] row-major
__device__ __nv_bfloat16 g_wkqhi[NBq*1024*Eq], g_wkqlo[NBq*1024*Eq];   // K|Q concat
__device__ __nv_bfloat16 g_wrhi[NBq*Eq*Eq], g_wrlo[NBq*Eq*Eq];
__device__ __nv_bfloat16 g_wmhi[NBq*Eq*Eq], g_wmlo[NBq*Eq*Eq];
__device__ __half        g_pjh[(size_t)Eq*VOC];                        // proj: single fp16

// ============================================================
// helpers
// ============================================================
__device__ __forceinline__ uint32_t smem_u32(const void* p) {
    uint32_t a;
    asm("{ .reg .u64 t; cvta.to.shared.u64 t, %1; cvt.u32.u64 %0, t; }"
        : "=r"(a) : "l"(p));
    return a;
}
__device__ __forceinline__ void ldsm4(uint32_t* r, uint32_t addr) {
    asm volatile("ldmatrix.sync.aligned.m8n8.x4.shared.b16 {%0,%1,%2,%3}, [%4];"
                 : "=r"(r[0]), "=r"(r[1]), "=r"(r[2]), "=r"(r[3]) : "r"(addr));
}
__device__ __forceinline__ void mma16816(float* c, const uint32_t* a, const uint32_t* b) {
    asm volatile(
        "mma.sync.aligned.m16n8k16.row.col.f32.bf16.bf16.f32 "
        "{%0,%1,%2,%3}, {%4,%5,%6,%7}, {%8,%9}, {%0,%1,%2,%3};"
        : "+f"(c[0]), "+f"(c[1]), "+f"(c[2]), "+f"(c[3])
        : "r"(a[0]), "r"(a[1]), "r"(a[2]), "r"(a[3]), "r"(b[0]), "r"(b[1]));
}
__device__ __forceinline__ void mma16816h(float* c, const uint32_t* a, const uint32_t* b) {
    asm volatile(
        "mma.sync.aligned.m16n8k16.row.col.f32.f16.f16.f32 "
        "{%0,%1,%2,%3}, {%4,%5,%6,%7}, {%8,%9}, {%0,%1,%2,%3};"
        : "+f"(c[0]), "+f"(c[1]), "+f"(c[2]), "+f"(c[3])
        : "r"(a[0]), "r"(a[1]), "r"(a[2]), "r"(a[3]), "r"(b[0]), "r"(b[1]));
}
#define CPASYNC(dst, src) \
    asm volatile("cp.async.cg.shared.global [%0], [%1], 16;" :: "r"(dst), "l"(src))
#define CPCOMMIT() asm volatile("cp.async.commit_group;" ::: "memory")
#define CPWAIT1()  asm volatile("cp.async.wait_group 1;" ::: "memory")
#define CPWAIT0()  asm volatile("cp.async.wait_group 0;" ::: "memory")

__device__ __forceinline__ uint32_t pack_hi2(float x, float y) {
    __nv_bfloat16 hx = __float2bfloat16(x), hy = __float2bfloat16(y);
    return (uint32_t)__bfloat16_as_ushort(hx) | ((uint32_t)__bfloat16_as_ushort(hy) << 16);
}
__device__ __forceinline__ uint32_t pack_lo2(float x, float y) {
    __nv_bfloat16 hx = __float2bfloat16(x), hy = __float2bfloat16(y);
    __nv_bfloat16 lx = __float2bfloat16(x - __bfloat162float(hx));
    __nv_bfloat16 ly = __float2bfloat16(y - __bfloat162float(hy));
    return (uint32_t)__bfloat16_as_ushort(lx) | ((uint32_t)__bfloat16_as_ushort(ly) << 16);
}
__device__ __forceinline__ uint32_t packh_hi2(float x, float y) {
    __half hx = __float2half_rn(x), hy = __float2half_rn(y);
    return (uint32_t)__half_as_ushort(hx) | ((uint32_t)__half_as_ushort(hy) << 16);
}
__device__ __forceinline__ uint32_t packh_lo2(float x, float y) {
    __half hx = __float2half_rn(x), hy = __float2half_rn(y);
    __half lx = __float2half_rn(x - __half2float(hx));
    __half ly = __float2half_rn(y - __half2float(hy));
    return (uint32_t)__half_as_ushort(lx) | ((uint32_t)__half_as_ushort(ly) << 16);
}

// ============================================================
// prep_all: ALL weight prep in ONE launch (32x32 transpose-split tiles)
// blocks [0,5120): bf16 hi/lo; blocks [5120,21120): projW -> single fp16
// ============================================================
__global__ __launch_bounds__(256) void prep_all(
    const float* __restrict__ Wk, const float* __restrict__ Wq,
    const float* __restrict__ Wres, const float* __restrict__ mlpW,
    const float* __restrict__ projW,
    __nv_bfloat16* __restrict__ kqhi, __nv_bfloat16* __restrict__ kqlo,
    __nv_bfloat16* __restrict__ rhi,  __nv_bfloat16* __restrict__ rlo,
    __nv_bfloat16* __restrict__ mhi,  __nv_bfloat16* __restrict__ mlo,
    __half* __restrict__ pj)
{
    __shared__ float t[32][33];
    int j = blockIdx.x;
    const float* src; int rs; size_t ibase, obase;
    __nv_bfloat16 *oh = nullptr, *ol = nullptr;
    bool projJob = false;

    if (j < 2560) {                       // Wk / Wq: [nbh][e][hd] -> [nb][1024][512]
        int q = (j >= 1280);
        int u = j - q * 1280;
        int nbh = u >> 5, tt = u & 31;
        int et = tt & 15, ht = tt >> 4;
        int nb = nbh >> 3, h = nbh & 7;
        int e0 = et * 32, hd0 = ht * 32;
        src   = q ? Wq : Wk;
        rs    = HDq;
        ibase = ((size_t)nbh * Eq + e0) * HDq + hd0;
        obase = ((size_t)nb * 1024 + q * 512 + h * HDq + hd0) * 512 + e0;
        oh = kqhi; ol = kqlo;
    } else if (j < 5120) {                // Wres / mlpW: [nb][k][n] -> [nb][512][512]
        int q = (j >= 3840);
        int u = j - 2560 - q * 1280;
        int nb = u >> 8, tt = u & 255;
        int nt = tt & 15, kt = tt >> 4;
        int n0 = nt * 32, k0 = kt * 32;
        src   = q ? mlpW : Wres;
        rs    = Eq;
        ibase = ((size_t)nb * Eq + k0) * Eq + n0;
        obase = ((size_t)nb * Eq + n0) * Eq + k0;
        oh = q ? mhi : rhi; ol = q ? mlo : rlo;
    } else {                              // projW [512][VOC] -> fp16 [VOC][512]
        int u = j - 5120;
        int nt = u % 1000, kt = u / 1000;
        int n0 = nt * 32, k0 = kt * 32;
        src   = projW;
        rs    = VOC;
        ibase = (size_t)k0 * VOC + n0;
        obase = (size_t)n0 * 512 + k0;
        projJob = true;
    }

    int lw = threadIdx.x >> 5, lc = threadIdx.x & 31;
    #pragma unroll
    for (int i = 0; i < 4; i++) {
        int r = lw + i * 8;
        t[r][lc] = src[ibase + (size_t)r * rs + lc];
    }
    __syncthreads();
    #pragma unroll
    for (int i = 0; i < 4; i++) {
        int c = lw + i * 8;
        float v = t[lc][c];
        size_t o = obase + (size_t)c * 512 + lc;
        if (projJob) {
            pj[o] = __float2half_rn(v);
        } else {
            __nv_bfloat16 h = __float2bfloat16(v);
            __nv_bfloat16 l = __float2bfloat16(v - __bfloat162float(h));
            oh[o] = h; ol[o] = l;
        }
    }
}

// ============================================================
// embedding: h = tok_emb[x] + pos_emb ; also write bf16 hi/lo split
// ============================================================
__global__ void embed_kernel(const int* __restrict__ x,
                             const float* __restrict__ tok,
                             const float* __restrict__ pos,
                             float* __restrict__ h,
                             __nv_bfloat16* __restrict__ ohi,
                             __nv_bfloat16* __restrict__ olo)
{
    int row = blockIdx.x;
    int t   = row & (Tq - 1);
    int idx = x[row];
    int tid = threadIdx.x;
    float4 a = ((const float4*)(tok + (size_t)idx * Eq))[tid];
    float4 p = ((const float4*)(pos + (size_t)t   * Eq))[tid];
    float4 o; o.x = a.x+p.x; o.y = a.y+p.y; o.z = a.z+p.z; o.w = a.w+p.w;
    ((float4*)(h + (size_t)row * Eq))[tid] = o;
    size_t e = (size_t)row * Eq + tid * 4;
    *(uint2*)(ohi + e) = make_uint2(pack_hi2(o.x, o.y), pack_hi2(o.z, o.w));
    *(uint2*)(olo + e) = make_uint2(pack_lo2(o.x, o.y), pack_lo2(o.z, o.w));
}

// ============================================================
// layernorm -> hi/lo split (HALF=false: bf16; true: fp16)
// ============================================================
template<bool HALF>
__global__ void ln_split_kernel(const float* __restrict__ in,
                                const float* __restrict__ g,
                                const float* __restrict__ b,
                                void* __restrict__ ohi_,
                                void* __restrict__ olo_)
{
    int row = blockIdx.x, tid = threadIdx.x;
    float4 v = ((const float4*)(in + (size_t)row * Eq))[tid];
    float s  = v.x + v.y + v.z + v.w;
    float sq = v.x*v.x + v.y*v.y + v.z*v.z + v.w*v.w;
    #pragma unroll
    for (int o = 16; o; o >>= 1) {
        s  += __shfl_xor_sync(0xffffffffu, s,  o);
        sq += __shfl_xor_sync(0xffffffffu, sq, o);
    }
    __shared__ float sm1[4], sm2[4];
    int wid = tid >> 5, lane = tid & 31;
    if (lane == 0) { sm1[wid] = s; sm2[wid] = sq; }
    __syncthreads();
    s  = sm1[0] + sm1[1] + sm1[2] + sm1[3];
    sq = sm2[0] + sm2[1] + sm2[2] + sm2[3];
    float mu   = s * (1.0f / Eq);
    float var  = sq * (1.0f / Eq) - mu * mu;
    float rstd = rsqrtf(var + 1e-5f);
    float4 gv = ((const float4*)g)[tid];
    float4 bv = ((const float4*)b)[tid];
    float4 o;
    o.x = (v.x - mu) * rstd * gv.x + bv.x;
    o.y = (v.y - mu) * rstd * gv.y + bv.y;
    o.z = (v.z - mu) * rstd * gv.z + bv.z;
    o.w = (v.w - mu) * rstd * gv.w + bv.w;
    size_t e = (size_t)row * Eq + tid * 4;
    if (HALF) {
        *(uint2*)((__half*)ohi_ + e) = make_uint2(packh_hi2(o.x, o.y), packh_hi2(o.z, o.w));
        *(uint2*)((__half*)olo_ + e) = make_uint2(packh_lo2(o.x, o.y), packh_lo2(o.z, o.w));
    } else {
        *(uint2*)((__nv_bfloat16*)ohi_ + e) = make_uint2(pack_hi2(o.x, o.y), pack_hi2(o.z, o.w));
        *(uint2*)((__nv_bfloat16*)olo_ + e) = make_uint2(pack_lo2(o.x, o.y), pack_lo2(o.z, o.w));
    }
}

// ============================================================
// bf16x3 HMMA GEMM (R12 committed-best): C[M,N] = A[M,512] @ W[512,N]
// 128x64x32 tile, 8 warps (4m x 2n), 2-stage cp.async,
// XOR-swizzled 64B rows, 48KB smem, 3 CTAs/SM.
// ============================================================
#define A_HI 0
#define A_LO 8192
#define B_HI 16384
#define B_LO 20480
#define STAGEB 24576
#define SMEMB  (2 * STAGEB)             // 49152

template<bool BIAS, bool RELU, bool RESID, bool OSPLIT>
__global__ __launch_bounds__(256, 3) void hgemm(
    const __nv_bfloat16* __restrict__ Ahi, const __nv_bfloat16* __restrict__ Alo,
    const __nv_bfloat16* __restrict__ Bhi, const __nv_bfloat16* __restrict__ Blo,
    const float* __restrict__ bias, const float* __restrict__ resid,
    float* __restrict__ C,
    __nv_bfloat16* __restrict__ Ohi, __nv_bfloat16* __restrict__ Olo,
    int N)
{
    extern __shared__ char dsm[];
    const uint32_t sb = smem_u32(dsm);
    const int tid = threadIdx.x;
    const int wid = tid >> 5, lane = tid & 31;
    const int wm = wid & 3, wn = wid >> 2;
    const int m0 = blockIdx.x * 128, n0 = blockIdx.y * 64;

    uint32_t aOff[2], bOff[2];
    {
        int ml = lane >> 3, r8 = lane & 7;
        int ar  = (ml & 1) * 8 + r8;
        int ac2 = ((ml >> 1) * 8) * 2;
        #pragma unroll
        for (int mi = 0; mi < 2; mi++) {
            int row = wm * 32 + mi * 16 + ar;
            aOff[mi] = (uint32_t)(row * 64 + (ac2 ^ (((row >> 1) & 3) << 4)));
        }
        int br  = (ml >> 1) * 8 + r8;
        int bc2 = ((ml & 1) * 8) * 2;
        #pragma unroll
        for (int j = 0; j < 2; j++) {
            int row = wn * 32 + j * 16 + br;
            bOff[j] = (uint32_t)(row * 64 + (bc2 ^ (((row >> 1) & 3) << 4)));
        }
    }

    auto loadStage = [&](int s) {
        uint32_t base = sb + (s & 1) * STAGEB;
        #pragma unroll
        for (int i = 0; i < 2; i++) {
            int idx = tid + i * 256;
            int row = idx >> 2, ch = idx & 3;
            uint32_t doff = (uint32_t)(row * 64 + ((ch ^ ((row >> 1) & 3)) << 4));
            size_t ga = (size_t)(m0 + row) * 512 + s * 32 + ch * 8;
            CPASYNC(base + A_HI + doff, Ahi + ga);
            CPASYNC(base + A_LO + doff, Alo + ga);
        }
        {
            int row = tid >> 2, ch = tid & 3;
            uint32_t doff = (uint32_t)(row * 64 + ((ch ^ ((row >> 1) & 3)) << 4));
            size_t gb = (size_t)(n0 + row) * 512 + s * 32 + ch * 8;
            CPASYNC(base + B_HI + doff, Bhi + gb);
            CPASYNC(base + B_LO + doff, Blo + gb);
        }
    };

    float acc[2][4][4];
    #pragma unroll
    for (int i = 0; i < 2; i++)
        #pragma unroll
        for (int j = 0; j < 4; j++)
            #pragma unroll
            for (int q = 0; q < 4; q++) acc[i][j][q] = 0.0f;

    loadStage(0); CPCOMMIT();

    for (int s = 0; s < 16; s++) {
        if (s + 1 < 16) { loadStage(s + 1); CPCOMMIT(); CPWAIT1(); }
        else            { CPWAIT0(); }
        __syncthreads();
        uint32_t base = sb + (s & 1) * STAGEB;
        #pragma unroll
        for (int kk = 0; kk < 2; kk++) {
            uint32_t kx = (uint32_t)(kk << 5);
            uint32_t ah[8], al[8], bh[8], bl[8];
            #pragma unroll
            for (int mi = 0; mi < 2; mi++) {
                ldsm4(ah + mi * 4, base + A_HI + (aOff[mi] ^ kx));
                ldsm4(al + mi * 4, base + A_LO + (aOff[mi] ^ kx));
            }
            #pragma unroll
            for (int j = 0; j < 2; j++) {
                ldsm4(bh + j * 4, base + B_HI + (bOff[j] ^ kx));
                ldsm4(bl + j * 4, base + B_LO + (bOff[j] ^ kx));
            }
            #pragma unroll
            for (int mi = 0; mi < 2; mi++)
                #pragma unroll
                for (int ni = 0; ni < 4; ni++) {
                    mma16816(acc[mi][ni], ah + mi * 4, bh + ni * 2);
                    mma16816(acc[mi][ni], ah + mi * 4, bl + ni * 2);
                    mma16816(acc[mi][ni], al + mi * 4, bh + ni * 2);
                }
        }
        __syncthreads();
    }

    const int r  = lane >> 2;
    const int cp = (lane & 3) * 2;
    #pragma unroll
    for (int mi = 0; mi < 2; mi++) {
        #pragma unroll
        for (int ni = 0; ni < 4; ni++) {
            int col  = n0 + wn * 32 + ni * 8 + cp;
            int row0 = m0 + wm * 32 + mi * 16 + r;
            #pragma unroll
            for (int hh = 0; hh < 2; hh++) {
                int row = row0 + hh * 8;
                float v0 = acc[mi][ni][hh * 2];
                float v1 = acc[mi][ni][hh * 2 + 1];
                if (BIAS) { v0 += bias[col]; v1 += bias[col + 1]; }
                if (RELU) { v0 = fmaxf(v0, 0.0f); v1 = fmaxf(v1, 0.0f); }
                if (RESID) {
                    float2 rr = *(const float2*)(resid + (size_t)row * N + col);
                    v0 += rr.x; v1 += rr.y;
                }
                *(float2*)(C + (size_t)row * N + col) = make_float2(v0, v1);
                if (OSPLIT) {
                    *(uint32_t*)(Ohi + (size_t)row * N + col) = pack_hi2(v0, v1);
                    *(uint32_t*)(Olo + (size_t)row * N + col) = pack_lo2(v0, v1);
                }
            }
        }
    }
}

// ============================================================
// fp16x2 HMMA GEMM (projection only): C = A @ W + bias
// A fp16 hi/lo [M][512]; B single fp16 [N][512].
// acc += Ahi*B + Alo*B  (2 passes, fp32 accumulate)
// Same tile/pipeline as hgemm; 3 streams -> 40KB smem.
// ============================================================
#define H_A_HI 0
#define H_A_LO 8192
#define H_B_S  16384
#define H_STAGEB 20480
#define H_SMEMB  (2 * H_STAGEB)         // 40960

__global__ __launch_bounds__(256, 3) void hgemm_h(
    const __half* __restrict__ Ahi, const __half* __restrict__ Alo,
    const __half* __restrict__ Bs,
    const float* __restrict__ bias,
    float* __restrict__ C, int N)
{
    extern __shared__ char dsm[];
    const uint32_t sb = smem_u32(dsm);
    const int tid = threadIdx.x;
    const int wid = tid >> 5, lane = tid & 31;
    const int wm = wid & 3, wn = wid >> 2;
    const int m0 = blockIdx.x * 128, n0 = blockIdx.y * 64;

    uint32_t aOff[2], bOff[2];
    {
        int ml = lane >> 3, r8 = lane & 7;
        int ar  = (ml & 1) * 8 + r8;
        int ac2 = ((ml >> 1) * 8) * 2;
        #pragma unroll
        for (int mi = 0; mi < 2; mi++) {
            int row = wm * 32 + mi * 16 + ar;
            aOff[mi] = (uint32_t)(row * 64 + (ac2 ^ (((row >> 1) & 3) << 4)));
        }
        int br  = (ml >> 1) * 8 + r8;
        int bc2 = ((ml & 1) * 8) * 2;
        #pragma unroll
        for (int j = 0; j < 2; j++) {
            int row = wn * 32 + j * 16 + br;
            bOff[j] = (uint32_t)(row * 64 + (bc2 ^ (((row >> 1) & 3) << 4)));
        }
    }

    auto loadStage = [&](int s) {
        uint32_t base = sb + (s & 1) * H_STAGEB;
        #pragma unroll
        for (int i = 0; i < 2; i++) {
            int idx = tid + i * 256;
            int row = idx >> 2, ch = idx & 3;
            uint32_t doff = (uint32_t)(row * 64 + ((ch ^ ((row >> 1) & 3)) << 4));
            size_t ga = (size_t)(m0 + row) * 512 + s * 32 + ch * 8;
            CPASYNC(base + H_A_HI + doff, Ahi + ga);
            CPASYNC(base + H_A_LO + doff, Alo + ga);
        }
        {
            int row = tid >> 2, ch = tid & 3;
            uint32_t doff = (uint32_t)(row * 64 + ((ch ^ ((row >> 1) & 3)) << 4));
            size_t gb = (size_t)(n0 + row) * 512 + s * 32 + ch * 8;
            CPASYNC(base + H_B_S + doff, Bs + gb);
        }
    };

    float acc[2][4][4];
    #pragma unroll
    for (int i = 0; i < 2; i++)
        #pragma unroll
        for (int j = 0; j < 4; j++)
            #pragma unroll
            for (int q = 0; q < 4; q++) acc[i][j][q] = 0.0f;

    loadStage(0); CPCOMMIT();

    for (int s = 0; s < 16; s++) {
        if (s + 1 < 16) { loadStage(s + 1); CPCOMMIT(); CPWAIT1(); }
        else            { CPWAIT0(); }
        __syncthreads();
        uint32_t base = sb + (s & 1) * H_STAGEB;
        #pragma unroll
        for (int kk = 0; kk < 2; kk++) {
            uint32_t kx = (uint32_t)(kk << 5);
            uint32_t ah[8], al[8], bs[8];
            #pragma unroll
            for (int mi = 0; mi < 2; mi++) {
                ldsm4(ah + mi * 4, base + H_A_HI + (aOff[mi] ^ kx));
                ldsm4(al + mi * 4, base + H_A_LO + (aOff[mi] ^ kx));
            }
            #pragma unroll
            for (int j = 0; j < 2; j++)
                ldsm4(bs + j * 4, base + H_B_S + (bOff[j] ^ kx));
            #pragma unroll
            for (int mi = 0; mi < 2; mi++)
                #pragma unroll
                for (int ni = 0; ni < 4; ni++) {
                    mma16816h(acc[mi][ni], ah + mi * 4, bs + ni * 2);
                    mma16816h(acc[mi][ni], al + mi * 4, bs + ni * 2);
                }
        }
        __syncthreads();
    }

    const int r  = lane >> 2;
    const int cp = (lane & 3) * 2;
    #pragma unroll
    for (int mi = 0; mi < 2; mi++) {
        #pragma unroll
        for (int ni = 0; ni < 4; ni++) {
            int col  = n0 + wn * 32 + ni * 8 + cp;
            int row0 = m0 + wm * 32 + mi * 16 + r;
            #pragma unroll
            for (int hh = 0; hh < 2; hh++) {
                int row = row0 + hh * 8;
                float v0 = acc[mi][ni][hh * 2]     + bias[col];
                float v1 = acc[mi][ni][hh * 2 + 1] + bias[col + 1];
                *(float2*)(C + (size_t)row * N + col) = make_float2(v0, v1);
            }
        }
    }
}

// ============================================================
// fused causal attention (quirks: scores = k[t]@q[s], v == q,
// scale = E^-0.5). KQ packed [M][1024] (K 0..511, Q 512..1023).
// No-max softmax; lane-parallel scoring; k in registers.
// ============================================================
__global__ __launch_bounds__(256) void attn_kernel(
    const float* __restrict__ KQ, float* __restrict__ O)
{
    __shared__ float2 qs2[128][34];
    int bh = blockIdx.y;
    int b = bh >> 3, h = bh & 7;
    int wid = threadIdx.x >> 5, lane = threadIdx.x & 31;
    int t = blockIdx.x * 8 + wid;
    const float scale = 0.044194173824159216f;    // 512^-0.5

    float kreg[64];
    {
        const float* kp = KQ + ((size_t)(b * Tq + t)) * 1024 + h * HDq;
        #pragma unroll
        for (int i = 0; i < 16; i++) {
            float4 v = *(const float4*)(kp + i * 4);
            kreg[i*4+0] = v.x * scale; kreg[i*4+1] = v.y * scale;
            kreg[i*4+2] = v.z * scale; kreg[i*4+3] = v.w * scale;
        }
    }

    float a0e = 0.f, a0o = 0.f, a1e = 0.f, a1o = 0.f, l = 0.f;
    int tmax = blockIdx.x * 8 + 7;

    for (int s0 = 0; s0 <= tmax; s0 += 128) {
        #pragma unroll
        for (int it = 0; it < 4; it++) {
            int idx = it * 256 + threadIdx.x;
            int row = idx >> 3, jj = idx & 7, c = jj * 4;
            const float* qp = KQ + (size_t)(b * Tq + s0 + row) * 1024 + 512 + h * HDq;
            float4 lo = *(const float4*)(qp + c);
            float4 hi = *(const float4*)(qp + c + 32);
            *(float4*)&qs2[row][c]     = make_float4(lo.x, hi.x, lo.y, hi.y);
            *(float4*)&qs2[row][c + 2] = make_float4(lo.z, hi.z, lo.w, hi.w);
        }
        __syncthreads();

        int send = min(127, t - s0);
        int nch = (send >> 5) + 1;
        for (int c = 0; c < nch; c++) {
            int sb32 = c * 32;
            int srow = sb32 + lane;
            const float2* qr = qs2[srow];
            float p0 = 0.f, p1 = 0.f, p2 = 0.f, p3 = 0.f;
            #pragma unroll
            for (int d2 = 0; d2 < 32; d2 += 4) {
                float4 A = *(const float4*)&qr[d2];
                float4 Bv = *(const float4*)&qr[d2 + 2];
                p0 = fmaf(kreg[d2],      A.x,  p0);
                p1 = fmaf(kreg[d2 + 32], A.y,  p1);
                p2 = fmaf(kreg[d2 + 1],  A.z,  p2);
                p3 = fmaf(kreg[d2 + 33], A.w,  p3);
                p0 = fmaf(kreg[d2 + 2],  Bv.x, p0);
                p1 = fmaf(kreg[d2 + 34], Bv.y, p1);
                p2 = fmaf(kreg[d2 + 3],  Bv.z, p2);
                p3 = fmaf(kreg[d2 + 35], Bv.w, p3);
            }
            float p = (p0 + p1) + (p2 + p3);
            float w = (srow <= send) ? __expf(p) : 0.0f;
            l += w;
            #pragma unroll
            for (int s2 = 0; s2 < 32; s2 += 2) {
                float w0 = __shfl_sync(0xffffffffu, w, s2);
                float w1 = __shfl_sync(0xffffffffu, w, s2 + 1);
                float2 q0 = qs2[sb32 + s2][lane];
                float2 q1 = qs2[sb32 + s2 + 1][lane];
                a0e = fmaf(w0, q0.x, a0e); a1e = fmaf(w0, q0.y, a1e);
                a0o = fmaf(w1, q1.x, a0o); a1o = fmaf(w1, q1.y, a1o);
            }
        }
        __syncthreads();
    }

    float lt = l;
    #pragma unroll
    for (int o = 16; o; o >>= 1)
        lt += __shfl_xor_sync(0xffffffffu, lt, o);
    float inv = 1.0f / lt;
    size_t obase = ((size_t)(b * Tq + t)) * Eq + h * HDq;
    O[obase + lane]      = (a0e + a0o) * inv;
    O[obase + lane + 32] = (a1e + a1o) * inv;
}

// ============================================================
// launch
// ============================================================
extern "C" void kernel_launch(void* const* d_in, const int* in_sizes, int n_in,
                              void* d_out, int out_size)
{
    const int*   x     = (const int*)  d_in[0];
    const float* tok   = (const float*)d_in[1];
    const float* pos   = (const float*)d_in[2];
    const float* Wk    = (const float*)d_in[3];
    const float* Wq    = (const float*)d_in[4];
    const float* Wres  = (const float*)d_in[5];
    const float* ln1g  = (const float*)d_in[6];
    const float* ln1b  = (const float*)d_in[7];
    const float* mlpW  = (const float*)d_in[8];
    const float* mlpb  = (const float*)d_in[9];
    const float* ln2g  = (const float*)d_in[10];
    const float* ln2b  = (const float*)d_in[11];
    const float* lnfg  = (const float*)d_in[12];
    const float* lnfb  = (const float*)d_in[13];
    const float* projW = (const float*)d_in[14];
    const float* projb = (const float*)d_in[15];
    float* out = (float*)d_out;

    float *h1, *h2, *kq, *mha;
    __nv_bfloat16 *h1hi, *h1lo, *hnhi, *hnlo;
    __nv_bfloat16 *wkqhi, *wkqlo, *wrhi, *wrlo, *wmhi, *wmlo;
    __half *pjh;
    cudaGetSymbolAddress((void**)&h1,  g_h1);
    cudaGetSymbolAddress((void**)&h2,  g_h2);
    cudaGetSymbolAddress((void**)&kq,  g_kq);
    cudaGetSymbolAddress((void**)&mha, g_mha);
    cudaGetSymbolAddress((void**)&h1hi, g_h1hi);
    cudaGetSymbolAddress((void**)&h1lo, g_h1lo);
    cudaGetSymbolAddress((void**)&hnhi, g_hnhi);
    cudaGetSymbolAddress((void**)&hnlo, g_hnlo);
    cudaGetSymbolAddress((void**)&wkqhi, g_wkqhi);
    cudaGetSymbolAddress((void**)&wkqlo, g_wkqlo);
    cudaGetSymbolAddress((void**)&wrhi, g_wrhi);
    cudaGetSymbolAddress((void**)&wrlo, g_wrlo);
    cudaGetSymbolAddress((void**)&wmhi, g_wmhi);
    cudaGetSymbolAddress((void**)&wmlo, g_wmlo);
    cudaGetSymbolAddress((void**)&pjh,  g_pjh);

    cudaFuncSetAttribute(hgemm<false,false,false,false>, cudaFuncAttributeMaxDynamicSharedMemorySize, SMEMB);
    cudaFuncSetAttribute(hgemm<false,false,true,false>,  cudaFuncAttributeMaxDynamicSharedMemorySize, SMEMB);
    cudaFuncSetAttribute(hgemm<true,true,true,true>,     cudaFuncAttributeMaxDynamicSharedMemorySize, SMEMB);
    cudaFuncSetAttribute(hgemm_h, cudaFuncAttributeMaxDynamicSharedMemorySize, H_SMEMB);

    prep_all<<<21120, 256>>>(Wk, Wq, Wres, mlpW, projW,
                             wkqhi, wkqlo, wrhi, wrlo, wmhi, wmlo, pjh);
    embed_kernel<<<MROWS, 128>>>(x, tok, pos, h1, h1hi, h1lo);

    dim3 gkq(MROWS / 128, 1024 / 64);            // 32 x 16 = 512 CTAs
    dim3 ge (MROWS / 128, Eq / 64);              // 32 x 8  = 256 CTAs
    for (int i = 0; i < NBq; i++) {
        const size_t wo   = (size_t)i * Eq * Eq;
        const size_t wokq = (size_t)i * 1024 * Eq;
        ln_split_kernel<false><<<MROWS, 128>>>(h1, ln1g + i * Eq, ln1b + i * Eq, hnhi, hnlo);
        hgemm<false,false,false,false><<<gkq, 256, SMEMB>>>(
            hnhi, hnlo, wkqhi + wokq, wkqlo + wokq, nullptr, nullptr, kq, nullptr, nullptr, 1024);
        attn_kernel<<<dim3(Tq / 8, Bq * Hq), 256>>>(kq, mha);
        hgemm<false,false,true,false><<<ge, 256, SMEMB>>>(
            h1hi, h1lo, wrhi + wo, wrlo + wo, nullptr, mha, h2, nullptr, nullptr, Eq);
        ln_split_kernel<false><<<MROWS, 128>>>(h2, ln2g + i * Eq, ln2b + i * Eq, hnhi, hnlo);
        hgemm<true,true,true,true><<<ge, 256, SMEMB>>>(
            hnhi, hnlo, wmhi + wo, wmlo + wo, mlpb + i * Eq, h2, h1, h1hi, h1lo, Eq);
    }

    // final LN emits fp16 splits (reusing hn buffers), projection in fp16x2
    ln_split_kernel<true><<<MROWS, 128>>>(h1, lnfg, lnfb, hnhi, hnlo);
    hgemm_h<<<dim3(MROWS / 128, VOC / 64), 256, H_SMEMB>>>(
        (const __half*)hnhi, (const __half*)hnlo, pjh, projb, out, VOC);
}

// round 16
// speedup vs baseline: 2.5158x; 2.2752x over previous
#include <cuda_runtime.h>
#include <cuda_bf16.h>
#include <cuda_fp16.h>
#include <cstdint>

// ---- problem constants ----
#define Bq   4
#define Tq   1024
#define Eq   512
#define Hq   8
#define HDq  64
#define NBq  5
#define VOC  32000
#define MROWS (Bq*Tq)          // 4096
#define KSCALE 0.044194173824159216f    // 512^-0.5

// ---- scratch (device globals; no allocations allowed) ----
__device__ float g_h1 [MROWS*Eq];
__device__ float g_h2 [MROWS*Eq];
__device__ float g_mha[MROWS*Eq];
__device__ __half g_kqh[MROWS*1024];    // fused K|Q output, fp16 (K pre-scaled)
// activation hi/lo splits (bf16 for blocks; final LN reuses as fp16)
__device__ __nv_bfloat16 g_h1hi[MROWS*Eq], g_h1lo[MROWS*Eq];
__device__ __nv_bfloat16 g_hnhi[MROWS*Eq], g_hnlo[MROWS*Eq];
// weight splits, transposed to [N][K=512] row-major
__device__ __nv_bfloat16 g_wkqhi[NBq*1024*Eq], g_wkqlo[NBq*1024*Eq];   // K|Q concat
__device__ __nv_bfloat16 g_wrhi[NBq*Eq*Eq], g_wrlo[NBq*Eq*Eq];
__device__ __nv_bfloat16 g_wmhi[NBq*Eq*Eq], g_wmlo[NBq*Eq*Eq];
__device__ __half        g_pjh[(size_t)Eq*VOC];                        // proj: single fp16

// ============================================================
// helpers
// ============================================================
__device__ __forceinline__ uint32_t smem_u32(const void* p) {
    uint32_t a;
    asm("{ .reg .u64 t; cvta.to.shared.u64 t, %1; cvt.u32.u64 %0, t; }"
        : "=r"(a) : "l"(p));
    return a;
}
__device__ __forceinline__ void ldsm4(uint32_t* r, uint32_t addr) {
    asm volatile("ldmatrix.sync.aligned.m8n8.x4.shared.b16 {%0,%1,%2,%3}, [%4];"
                 : "=r"(r[0]), "=r"(r[1]), "=r"(r[2]), "=r"(r[3]) : "r"(addr));
}
__device__ __forceinline__ void ldsm4t(uint32_t* r, uint32_t addr) {
    asm volatile("ldmatrix.sync.aligned.m8n8.x4.trans.shared.b16 {%0,%1,%2,%3}, [%4];"
                 : "=r"(r[0]), "=r"(r[1]), "=r"(r[2]), "=r"(r[3]) : "r"(addr));
}
__device__ __forceinline__ void mma16816(float* c, const uint32_t* a, const uint32_t* b) {
    asm volatile(
        "mma.sync.aligned.m16n8k16.row.col.f32.bf16.bf16.f32 "
        "{%0,%1,%2,%3}, {%4,%5,%6,%7}, {%8,%9}, {%0,%1,%2,%3};"
        : "+f"(c[0]), "+f"(c[1]), "+f"(c[2]), "+f"(c[3])
        : "r"(a[0]), "r"(a[1]), "r"(a[2]), "r"(a[3]), "r"(b[0]), "r"(b[1]));
}
__device__ __forceinline__ void mma16816h(float* c, const uint32_t* a, const uint32_t* b) {
    asm volatile(
        "mma.sync.aligned.m16n8k16.row.col.f32.f16.f16.f32 "
        "{%0,%1,%2,%3}, {%4,%5,%6,%7}, {%8,%9}, {%0,%1,%2,%3};"
        : "+f"(c[0]), "+f"(c[1]), "+f"(c[2]), "+f"(c[3])
        : "r"(a[0]), "r"(a[1]), "r"(a[2]), "r"(a[3]), "r"(b[0]), "r"(b[1]));
}
#define CPASYNC(dst, src) \
    asm volatile("cp.async.cg.shared.global [%0], [%1], 16;" :: "r"(dst), "l"(src))
#define CPCOMMIT() asm volatile("cp.async.commit_group;" ::: "memory")
#define CPWAIT1()  asm volatile("cp.async.wait_group 1;" ::: "memory")
#define CPWAIT0()  asm volatile("cp.async.wait_group 0;" ::: "memory")

__device__ __forceinline__ uint32_t pack_hi2(float x, float y) {
    __nv_bfloat16 hx = __float2bfloat16(x), hy = __float2bfloat16(y);
    return (uint32_t)__bfloat16_as_ushort(hx) | ((uint32_t)__bfloat16_as_ushort(hy) << 16);
}
__device__ __forceinline__ uint32_t pack_lo2(float x, float y) {
    __nv_bfloat16 hx = __float2bfloat16(x), hy = __float2bfloat16(y);
    __nv_bfloat16 lx = __float2bfloat16(x - __bfloat162float(hx));
    __nv_bfloat16 ly = __float2bfloat16(y - __bfloat162float(hy));
    return (uint32_t)__bfloat16_as_ushort(lx) | ((uint32_t)__bfloat16_as_ushort(ly) << 16);
}
__device__ __forceinline__ uint32_t packh_hi2(float x, float y) {
    __half hx = __float2half_rn(x), hy = __float2half_rn(y);
    return (uint32_t)__half_as_ushort(hx) | ((uint32_t)__half_as_ushort(hy) << 16);
}
__device__ __forceinline__ uint32_t packh_lo2(float x, float y) {
    __half hx = __float2half_rn(x), hy = __float2half_rn(y);
    __half lx = __float2half_rn(x - __half2float(hx));
    __half ly = __float2half_rn(y - __half2float(hy));
    return (uint32_t)__half_as_ushort(lx) | ((uint32_t)__half_as_ushort(ly) << 16);
}

// ============================================================
// prep_all: ALL weight prep in ONE launch (32x32 transpose-split tiles)
// ============================================================
__global__ __launch_bounds__(256) void prep_all(
    const float* __restrict__ Wk, const float* __restrict__ Wq,
    const float* __restrict__ Wres, const float* __restrict__ mlpW,
    const float* __restrict__ projW,
    __nv_bfloat16* __restrict__ kqhi, __nv_bfloat16* __restrict__ kqlo,
    __nv_bfloat16* __restrict__ rhi,  __nv_bfloat16* __restrict__ rlo,
    __nv_bfloat16* __restrict__ mhi,  __nv_bfloat16* __restrict__ mlo,
    __half* __restrict__ pj)
{
    __shared__ float t[32][33];
    int j = blockIdx.x;
    const float* src; int rs; size_t ibase, obase;
    __nv_bfloat16 *oh = nullptr, *ol = nullptr;
    bool projJob = false;

    if (j < 2560) {                       // Wk / Wq: [nbh][e][hd] -> [nb][1024][512]
        int q = (j >= 1280);
        int u = j - q * 1280;
        int nbh = u >> 5, tt = u & 31;
        int et = tt & 15, ht = tt >> 4;
        int nb = nbh >> 3, h = nbh & 7;
        int e0 = et * 32, hd0 = ht * 32;
        src   = q ? Wq : Wk;
        rs    = HDq;
        ibase = ((size_t)nbh * Eq + e0) * HDq + hd0;
        obase = ((size_t)nb * 1024 + q * 512 + h * HDq + hd0) * 512 + e0;
        oh = kqhi; ol = kqlo;
    } else if (j < 5120) {                // Wres / mlpW: [nb][k][n] -> [nb][512][512]
        int q = (j >= 3840);
        int u = j - 2560 - q * 1280;
        int nb = u >> 8, tt = u & 255;
        int nt = tt & 15, kt = tt >> 4;
        int n0 = nt * 32, k0 = kt * 32;
        src   = q ? mlpW : Wres;
        rs    = Eq;
        ibase = ((size_t)nb * Eq + k0) * Eq + n0;
        obase = ((size_t)nb * Eq + n0) * Eq + k0;
        oh = q ? mhi : rhi; ol = q ? mlo : rlo;
    } else {                              // projW [512][VOC] -> fp16 [VOC][512]
        int u = j - 5120;
        int nt = u % 1000, kt = u / 1000;
        int n0 = nt * 32, k0 = kt * 32;
        src   = projW;
        rs    = VOC;
        ibase = (size_t)k0 * VOC + n0;
        obase = (size_t)n0 * 512 + k0;
        projJob = true;
    }

    int lw = threadIdx.x >> 5, lc = threadIdx.x & 31;
    #pragma unroll
    for (int i = 0; i < 4; i++) {
        int r = lw + i * 8;
        t[r][lc] = src[ibase + (size_t)r * rs + lc];
    }
    __syncthreads();
    #pragma unroll
    for (int i = 0; i < 4; i++) {
        int c = lw + i * 8;
        float v = t[lc][c];
        size_t o = obase + (size_t)c * 512 + lc;
        if (projJob) {
            pj[o] = __float2half_rn(v);
        } else {
            __nv_bfloat16 h = __float2bfloat16(v);
            __nv_bfloat16 l = __float2bfloat16(v - __bfloat162float(h));
            oh[o] = h; ol[o] = l;
        }
    }
}

// ============================================================
// embedding: h = tok_emb[x] + pos_emb ; also write bf16 hi/lo split
// ============================================================
__global__ void embed_kernel(const int* __restrict__ x,
                             const float* __restrict__ tok,
                             const float* __restrict__ pos,
                             float* __restrict__ h,
                             __nv_bfloat16* __restrict__ ohi,
                             __nv_bfloat16* __restrict__ olo)
{
    int row = blockIdx.x;
    int t   = row & (Tq - 1);
    int idx = x[row];
    int tid = threadIdx.x;
    float4 a = ((const float4*)(tok + (size_t)idx * Eq))[tid];
    float4 p = ((const float4*)(pos + (size_t)t   * Eq))[tid];
    float4 o; o.x = a.x+p.x; o.y = a.y+p.y; o.z = a.z+p.z; o.w = a.w+p.w;
    ((float4*)(h + (size_t)row * Eq))[tid] = o;
    size_t e = (size_t)row * Eq + tid * 4;
    *(uint2*)(ohi + e) = make_uint2(pack_hi2(o.x, o.y), pack_hi2(o.z, o.w));
    *(uint2*)(olo + e) = make_uint2(pack_lo2(o.x, o.y), pack_lo2(o.z, o.w));
}

// ============================================================
// layernorm -> hi/lo split (HALF=false: bf16; true: fp16)
// ============================================================
template<bool HALF>
__global__ void ln_split_kernel(const float* __restrict__ in,
                                const float* __restrict__ g,
                                const float* __restrict__ b,
                                void* __restrict__ ohi_,
                                void* __restrict__ olo_)
{
    int row = blockIdx.x, tid = threadIdx.x;
    float4 v = ((const float4*)(in + (size_t)row * Eq))[tid];
    float s  = v.x + v.y + v.z + v.w;
    float sq = v.x*v.x + v.y*v.y + v.z*v.z + v.w*v.w;
    #pragma unroll
    for (int o = 16; o; o >>= 1) {
        s  += __shfl_xor_sync(0xffffffffu, s,  o);
        sq += __shfl_xor_sync(0xffffffffu, sq, o);
    }
    __shared__ float sm1[4], sm2[4];
    int wid = tid >> 5, lane = tid & 31;
    if (lane == 0) { sm1[wid] = s; sm2[wid] = sq; }
    __syncthreads();
    s  = sm1[0] + sm1[1] + sm1[2] + sm1[3];
    sq = sm2[0] + sm2[1] + sm2[2] + sm2[3];
    float mu   = s * (1.0f / Eq);
    float var  = sq * (1.0f / Eq) - mu * mu;
    float rstd = rsqrtf(var + 1e-5f);
    float4 gv = ((const float4*)g)[tid];
    float4 bv = ((const float4*)b)[tid];
    float4 o;
    o.x = (v.x - mu) * rstd * gv.x + bv.x;
    o.y = (v.y - mu) * rstd * gv.y + bv.y;
    o.z = (v.z - mu) * rstd * gv.z + bv.z;
    o.w = (v.w - mu) * rstd * gv.w + bv.w;
    size_t e = (size_t)row * Eq + tid * 4;
    if (HALF) {
        *(uint2*)((__half*)ohi_ + e) = make_uint2(packh_hi2(o.x, o.y), packh_hi2(o.z, o.w));
        *(uint2*)((__half*)olo_ + e) = make_uint2(packh_lo2(o.x, o.y), packh_lo2(o.z, o.w));
    } else {
        *(uint2*)((__nv_bfloat16*)ohi_ + e) = make_uint2(pack_hi2(o.x, o.y), pack_hi2(o.z, o.w));
        *(uint2*)((__nv_bfloat16*)olo_ + e) = make_uint2(pack_lo2(o.x, o.y), pack_lo2(o.z, o.w));
    }
}

// ============================================================
// bf16x3 HMMA GEMM: C[M,N] = A[M,512] @ W[512,N]
// 128x64x32 tile, 8 warps (4m x 2n), 2-stage cp.async,
// XOR-swizzled 64B rows, 48KB smem, 3 CTAs/SM.
// KQH: write fp16 to Ckq [M][1024], K half (cols<512) pre-scaled.
// ============================================================
#define A_HI 0
#define A_LO 8192
#define B_HI 16384
#define B_LO 20480
#define STAGEB 24576
#define SMEMB  (2 * STAGEB)             // 49152

template<bool BIAS, bool RELU, bool RESID, bool OSPLIT, bool KQH>
__global__ __launch_bounds__(256, 3) void hgemm(
    const __nv_bfloat16* __restrict__ Ahi, const __nv_bfloat16* __restrict__ Alo,
    const __nv_bfloat16* __restrict__ Bhi, const __nv_bfloat16* __restrict__ Blo,
    const float* __restrict__ bias, const float* __restrict__ resid,
    float* __restrict__ C,
    __nv_bfloat16* __restrict__ Ohi, __nv_bfloat16* __restrict__ Olo,
    __half* __restrict__ Ckq,
    int N)
{
    extern __shared__ char dsm[];
    const uint32_t sb = smem_u32(dsm);
    const int tid = threadIdx.x;
    const int wid = tid >> 5, lane = tid & 31;
    const int wm = wid & 3, wn = wid >> 2;
    const int m0 = blockIdx.x * 128, n0 = blockIdx.y * 64;

    uint32_t aOff[2], bOff[2];
    {
        int ml = lane >> 3, r8 = lane & 7;
        int ar  = (ml & 1) * 8 + r8;
        int ac2 = ((ml >> 1) * 8) * 2;
        #pragma unroll
        for (int mi = 0; mi < 2; mi++) {
            int row = wm * 32 + mi * 16 + ar;
            aOff[mi] = (uint32_t)(row * 64 + (ac2 ^ (((row >> 1) & 3) << 4)));
        }
        int br  = (ml >> 1) * 8 + r8;
        int bc2 = ((ml & 1) * 8) * 2;
        #pragma unroll
        for (int j = 0; j < 2; j++) {
            int row = wn * 32 + j * 16 + br;
            bOff[j] = (uint32_t)(row * 64 + (bc2 ^ (((row >> 1) & 3) << 4)));
        }
    }

    auto loadStage = [&](int s) {
        uint32_t base = sb + (s & 1) * STAGEB;
        #pragma unroll
        for (int i = 0; i < 2; i++) {
            int idx = tid + i * 256;
            int row = idx >> 2, ch = idx & 3;
            uint32_t doff = (uint32_t)(row * 64 + ((ch ^ ((row >> 1) & 3)) << 4));
            size_t ga = (size_t)(m0 + row) * 512 + s * 32 + ch * 8;
            CPASYNC(base + A_HI + doff, Ahi + ga);
            CPASYNC(base + A_LO + doff, Alo + ga);
        }
        {
            int row = tid >> 2, ch = tid & 3;
            uint32_t doff = (uint32_t)(row * 64 + ((ch ^ ((row >> 1) & 3)) << 4));
            size_t gb = (size_t)(n0 + row) * 512 + s * 32 + ch * 8;
            CPASYNC(base + B_HI + doff, Bhi + gb);
            CPASYNC(base + B_LO + doff, Blo + gb);
        }
    };

    float acc[2][4][4];
    #pragma unroll
    for (int i = 0; i < 2; i++)
        #pragma unroll
        for (int j = 0; j < 4; j++)
            #pragma unroll
            for (int q = 0; q < 4; q++) acc[i][j][q] = 0.0f;

    loadStage(0); CPCOMMIT();

    for (int s = 0; s < 16; s++) {
        if (s + 1 < 16) { loadStage(s + 1); CPCOMMIT(); CPWAIT1(); }
        else            { CPWAIT0(); }
        __syncthreads();
        uint32_t base = sb + (s & 1) * STAGEB;
        #pragma unroll
        for (int kk = 0; kk < 2; kk++) {
            uint32_t kx = (uint32_t)(kk << 5);
            uint32_t ah[8], al[8], bh[8], bl[8];
            #pragma unroll
            for (int mi = 0; mi < 2; mi++) {
                ldsm4(ah + mi * 4, base + A_HI + (aOff[mi] ^ kx));
                ldsm4(al + mi * 4, base + A_LO + (aOff[mi] ^ kx));
            }
            #pragma unroll
            for (int j = 0; j < 2; j++) {
                ldsm4(bh + j * 4, base + B_HI + (bOff[j] ^ kx));
                ldsm4(bl + j * 4, base + B_LO + (bOff[j] ^ kx));
            }
            #pragma unroll
            for (int mi = 0; mi < 2; mi++)
                #pragma unroll
                for (int ni = 0; ni < 4; ni++) {
                    mma16816(acc[mi][ni], ah + mi * 4, bh + ni * 2);
                    mma16816(acc[mi][ni], ah + mi * 4, bl + ni * 2);
                    mma16816(acc[mi][ni], al + mi * 4, bh + ni * 2);
                }
        }
        __syncthreads();
    }

    const int r  = lane >> 2;
    const int cp = (lane & 3) * 2;
    #pragma unroll
    for (int mi = 0; mi < 2; mi++) {
        #pragma unroll
        for (int ni = 0; ni < 4; ni++) {
            int col  = n0 + wn * 32 + ni * 8 + cp;
            int row0 = m0 + wm * 32 + mi * 16 + r;
            #pragma unroll
            for (int hh = 0; hh < 2; hh++) {
                int row = row0 + hh * 8;
                float v0 = acc[mi][ni][hh * 2];
                float v1 = acc[mi][ni][hh * 2 + 1];
                if (KQH) {
                    float sc = (col < 512) ? KSCALE : 1.0f;
                    *(uint32_t*)(Ckq + (size_t)row * 1024 + col) = packh_hi2(v0 * sc, v1 * sc);
                } else {
                    if (BIAS) { v0 += bias[col]; v1 += bias[col + 1]; }
                    if (RELU) { v0 = fmaxf(v0, 0.0f); v1 = fmaxf(v1, 0.0f); }
                    if (RESID) {
                        float2 rr = *(const float2*)(resid + (size_t)row * N + col);
                        v0 += rr.x; v1 += rr.y;
                    }
                    *(float2*)(C + (size_t)row * N + col) = make_float2(v0, v1);
                    if (OSPLIT) {
                        *(uint32_t*)(Ohi + (size_t)row * N + col) = pack_hi2(v0, v1);
                        *(uint32_t*)(Olo + (size_t)row * N + col) = pack_lo2(v0, v1);
                    }
                }
            }
        }
    }
}

// ============================================================
// fp16x2 HMMA GEMM (projection only): C = A @ W + bias
// ============================================================
#define H_A_HI 0
#define H_A_LO 8192
#define H_B_S  16384
#define H_STAGEB 20480
#define H_SMEMB  (2 * H_STAGEB)         // 40960

__global__ __launch_bounds__(256, 3) void hgemm_h(
    const __half* __restrict__ Ahi, const __half* __restrict__ Alo,
    const __half* __restrict__ Bs,
    const float* __restrict__ bias,
    float* __restrict__ C, int N)
{
    extern __shared__ char dsm[];
    const uint32_t sb = smem_u32(dsm);
    const int tid = threadIdx.x;
    const int wid = tid >> 5, lane = tid & 31;
    const int wm = wid & 3, wn = wid >> 2;
    const int m0 = blockIdx.x * 128, n0 = blockIdx.y * 64;

    uint32_t aOff[2], bOff[2];
    {
        int ml = lane >> 3, r8 = lane & 7;
        int ar  = (ml & 1) * 8 + r8;
        int ac2 = ((ml >> 1) * 8) * 2;
        #pragma unroll
        for (int mi = 0; mi < 2; mi++) {
            int row = wm * 32 + mi * 16 + ar;
            aOff[mi] = (uint32_t)(row * 64 + (ac2 ^ (((row >> 1) & 3) << 4)));
        }
        int br  = (ml >> 1) * 8 + r8;
        int bc2 = ((ml & 1) * 8) * 2;
        #pragma unroll
        for (int j = 0; j < 2; j++) {
            int row = wn * 32 + j * 16 + br;
            bOff[j] = (uint32_t)(row * 64 + (bc2 ^ (((row >> 1) & 3) << 4)));
        }
    }

    auto loadStage = [&](int s) {
        uint32_t base = sb + (s & 1) * H_STAGEB;
        #pragma unroll
        for (int i = 0; i < 2; i++) {
            int idx = tid + i * 256;
            int row = idx >> 2, ch = idx & 3;
            uint32_t doff = (uint32_t)(row * 64 + ((ch ^ ((row >> 1) & 3)) << 4));
            size_t ga = (size_t)(m0 + row) * 512 + s * 32 + ch * 8;
            CPASYNC(base + H_A_HI + doff, Ahi + ga);
            CPASYNC(base + H_A_LO + doff, Alo + ga);
        }
        {
            int row = tid >> 2, ch = tid & 3;
            uint32_t doff = (uint32_t)(row * 64 + ((ch ^ ((row >> 1) & 3)) << 4));
            size_t gb = (size_t)(n0 + row) * 512 + s * 32 + ch * 8;
            CPASYNC(base + H_B_S + doff, Bs + gb);
        }
    };

    float acc[2][4][4];
    #pragma unroll
    for (int i = 0; i < 2; i++)
        #pragma unroll
        for (int j = 0; j < 4; j++)
            #pragma unroll
            for (int q = 0; q < 4; q++) acc[i][j][q] = 0.0f;

    loadStage(0); CPCOMMIT();

    for (int s = 0; s < 16; s++) {
        if (s + 1 < 16) { loadStage(s + 1); CPCOMMIT(); CPWAIT1(); }
        else            { CPWAIT0(); }
        __syncthreads();
        uint32_t base = sb + (s & 1) * H_STAGEB;
        #pragma unroll
        for (int kk = 0; kk < 2; kk++) {
            uint32_t kx = (uint32_t)(kk << 5);
            uint32_t ah[8], al[8], bs[8];
            #pragma unroll
            for (int mi = 0; mi < 2; mi++) {
                ldsm4(ah + mi * 4, base + H_A_HI + (aOff[mi] ^ kx));
                ldsm4(al + mi * 4, base + H_A_LO + (aOff[mi] ^ kx));
            }
            #pragma unroll
            for (int j = 0; j < 2; j++)
                ldsm4(bs + j * 4, base + H_B_S + (bOff[j] ^ kx));
            #pragma unroll
            for (int mi = 0; mi < 2; mi++)
                #pragma unroll
                for (int ni = 0; ni < 4; ni++) {
                    mma16816h(acc[mi][ni], ah + mi * 4, bs + ni * 2);
                    mma16816h(acc[mi][ni], al + mi * 4, bs + ni * 2);
                }
        }
        __syncthreads();
    }

    const int r  = lane >> 2;
    const int cp = (lane & 3) * 2;
    #pragma unroll
    for (int mi = 0; mi < 2; mi++) {
        #pragma unroll
        for (int ni = 0; ni < 4; ni++) {
            int col  = n0 + wn * 32 + ni * 8 + cp;
            int row0 = m0 + wm * 32 + mi * 16 + r;
            #pragma unroll
            for (int hh = 0; hh < 2; hh++) {
                int row = row0 + hh * 8;
                float v0 = acc[mi][ni][hh * 2]     + bias[col];
                float v1 = acc[mi][ni][hh * 2 + 1] + bias[col + 1];
                *(float2*)(C + (size_t)row * N + col) = make_float2(v0, v1);
            }
        }
    }
}

// ============================================================
// flash attention via warp-MMA (quirks: S = K@Q^T, V == Q,
// scale pre-folded into fp16 K). No-max softmax: O and l
// accumulate associatively across s-tiles, no rescaling.
// CTA = 64 query rows x one (b,h); 4 warps x m16.
// grid (T/64, B*H) = (16, 32), 128 threads.
// KQ fp16 [M][1024] (K 0..511 scaled, Q 512..1023).
// ============================================================
__global__ __launch_bounds__(128) void flash_attn(
    const __half* __restrict__ KQ, float* __restrict__ O)
{
    __shared__ __align__(16) char smem[3 * 8192];    // K tile + Q double buffer
    uint32_t sb = smem_u32(smem);
    const uint32_t kbuf = sb, qbuf = sb + 8192;
    int tid = threadIdx.x;
    int w = tid >> 5, lane = tid & 31;
    int tt = blockIdx.x;
    int bh = blockIdx.y;
    int b = bh >> 3, h = bh & 7;
    int t0 = tt * 64;
    size_t rowbase = (size_t)b * Tq;

    // K tile: 64 rows x 64 halves (128B rows), chunk swizzle c^(r&7)
    #pragma unroll
    for (int i = 0; i < 4; i++) {
        int idx = tid + i * 128;
        int r = idx >> 3, c = idx & 7;
        CPASYNC(kbuf + r * 128 + ((c ^ (r & 7)) << 4),
                KQ + (rowbase + t0 + r) * 1024 + h * HDq + c * 8);
    }
    CPCOMMIT();

    auto loadQ = [&](int st) {
        uint32_t dst = qbuf + (st & 1) * 8192;
        int s0 = st * 64;
        #pragma unroll
        for (int i = 0; i < 4; i++) {
            int idx = tid + i * 128;
            int r = idx >> 3, c = idx & 7;
            CPASYNC(dst + r * 128 + ((c ^ (r & 7)) << 4),
                    KQ + (rowbase + s0 + r) * 1024 + 512 + h * HDq + c * 8);
        }
        CPCOMMIT();
    };
    loadQ(0);

    const int ml = lane >> 3, r8 = lane & 7;
    // K A-frag addresses: row = w*16 + (ml&1)*8 + r8, chunk = 2ks + (ml>>1)
    uint32_t kf[4][4];
    {
        int kr = w * 16 + (ml & 1) * 8 + r8;
        int kc = ml >> 1;
        CPWAIT1();            // K done (older group), Q0 may be in flight
        __syncthreads();
        #pragma unroll
        for (int ks = 0; ks < 4; ks++)
            ldsm4(kf[ks], kbuf + kr * 128 + (((2 * ks + kc) ^ (kr & 7)) << 4));
    }

    // Q score-B frag: row = 16j + (ml>>1)*8 + r8, chunk = 2ks + (ml&1)
    const int qrA = (ml >> 1) * 8 + r8;
    const int qcm = ml & 1;
    // V trans-B frag: row = 16ks + (ml&1)*8 + r8, chunk = 2j + (ml>>1)
    const int vrA = (ml & 1) * 8 + r8;
    const int vcm = ml >> 1;

    float Oa[8][4];
    #pragma unroll
    for (int f = 0; f < 8; f++)
        #pragma unroll
        for (int q = 0; q < 4; q++) Oa[f][q] = 0.0f;
    float l0 = 0.0f, l1 = 0.0f;

    for (int st = 0; st <= tt; st++) {
        if (st < tt) { loadQ(st + 1); CPWAIT1(); }
        else         { CPWAIT0(); }
        __syncthreads();
        uint32_t base = qbuf + (st & 1) * 8192;

        // S = K @ Q^T  (m=t16, n=s64, k=d64)
        float S[8][4];
        #pragma unroll
        for (int f = 0; f < 8; f++)
            #pragma unroll
            for (int q = 0; q < 4; q++) S[f][q] = 0.0f;
        #pragma unroll
        for (int ks = 0; ks < 4; ks++) {
            uint32_t qf[16];
            #pragma unroll
            for (int j = 0; j < 4; j++) {
                int rr = 16 * j + qrA;
                ldsm4(qf + j * 4, base + rr * 128 + (((2 * ks + qcm) ^ (rr & 7)) << 4));
            }
            #pragma unroll
            for (int f = 0; f < 8; f++)
                mma16816h(S[f], kf[ks], qf + f * 2);
        }

        // mask (diagonal tile) + exp + rowsum
        if (st == tt) {
            int tl = w * 16 + (lane >> 2);
            #pragma unroll
            for (int f = 0; f < 8; f++) {
                int c0 = 8 * f + 2 * (lane & 3);
                float w0 = (c0     <= tl)     ? __expf(S[f][0]) : 0.0f;
                float w1 = (c0 + 1 <= tl)     ? __expf(S[f][1]) : 0.0f;
                float w2 = (c0     <= tl + 8) ? __expf(S[f][2]) : 0.0f;
                float w3 = (c0 + 1 <= tl + 8) ? __expf(S[f][3]) : 0.0f;
                S[f][0] = w0; S[f][1] = w1; S[f][2] = w2; S[f][3] = w3;
                l0 += w0 + w1; l1 += w2 + w3;
            }
        } else {
            #pragma unroll
            for (int f = 0; f < 8; f++) {
                float w0 = __expf(S[f][0]), w1 = __expf(S[f][1]);
                float w2 = __expf(S[f][2]), w3 = __expf(S[f][3]);
                S[f][0] = w0; S[f][1] = w1; S[f][2] = w2; S[f][3] = w3;
                l0 += w0 + w1; l1 += w2 + w3;
            }
        }

        // pack P (accumulator layout == A-operand layout)
        uint32_t pa[4][4];
        #pragma unroll
        for (int ks = 0; ks < 4; ks++) {
            pa[ks][0] = packh_hi2(S[2*ks][0],     S[2*ks][1]);
            pa[ks][1] = packh_hi2(S[2*ks][2],     S[2*ks][3]);
            pa[ks][2] = packh_hi2(S[2*ks+1][0],   S[2*ks+1][1]);
            pa[ks][3] = packh_hi2(S[2*ks+1][2],   S[2*ks+1][3]);
        }

        // O += P @ V  (V = Q, trans ldmatrix gives V^T as B)
        #pragma unroll
        for (int ks = 0; ks < 4; ks++) {
            uint32_t vf[16];
            int rr = 16 * ks + vrA;
            #pragma unroll
            for (int j = 0; j < 4; j++)
                ldsm4t(vf + j * 4, base + rr * 128 + (((2 * j + vcm) ^ (rr & 7)) << 4));
            #pragma unroll
            for (int f = 0; f < 8; f++)
                mma16816h(Oa[f], pa[ks], vf + f * 2);
        }
        __syncthreads();
    }

    // reduce l across the quad (lanes sharing row g)
    l0 += __shfl_xor_sync(0xffffffffu, l0, 1);
    l0 += __shfl_xor_sync(0xffffffffu, l0, 2);
    l1 += __shfl_xor_sync(0xffffffffu, l1, 1);
    l1 += __shfl_xor_sync(0xffffffffu, l1, 2);
    float i0 = 1.0f / l0, i1 = 1.0f / l1;

    size_t rg = rowbase + t0 + w * 16 + (lane >> 2);
    int cb = h * HDq + 2 * (lane & 3);
    #pragma unroll
    for (int f = 0; f < 8; f++) {
        *(float2*)&O[rg * Eq + cb + 8 * f] =
            make_float2(Oa[f][0] * i0, Oa[f][1] * i0);
        *(float2*)&O[(rg + 8) * Eq + cb + 8 * f] =
            make_float2(Oa[f][2] * i1, Oa[f][3] * i1);
    }
}

// ============================================================
// launch
// ============================================================
extern "C" void kernel_launch(void* const* d_in, const int* in_sizes, int n_in,
                              void* d_out, int out_size)
{
    const int*   x     = (const int*)  d_in[0];
    const float* tok   = (const float*)d_in[1];
    const float* pos   = (const float*)d_in[2];
    const float* Wk    = (const float*)d_in[3];
    const float* Wq    = (const float*)d_in[4];
    const float* Wres  = (const float*)d_in[5];
    const float* ln1g  = (const float*)d_in[6];
    const float* ln1b  = (const float*)d_in[7];
    const float* mlpW  = (const float*)d_in[8];
    const float* mlpb  = (const float*)d_in[9];
    const float* ln2g  = (const float*)d_in[10];
    const float* ln2b  = (const float*)d_in[11];
    const float* lnfg  = (const float*)d_in[12];
    const float* lnfb  = (const float*)d_in[13];
    const float* projW = (const float*)d_in[14];
    const float* projb = (const float*)d_in[15];
    float* out = (float*)d_out;

    float *h1, *h2, *mha;
    __half *kqh, *pjh;
    __nv_bfloat16 *h1hi, *h1lo, *hnhi, *hnlo;
    __nv_bfloat16 *wkqhi, *wkqlo, *wrhi, *wrlo, *wmhi, *wmlo;
    cudaGetSymbolAddress((void**)&h1,  g_h1);
    cudaGetSymbolAddress((void**)&h2,  g_h2);
    cudaGetSymbolAddress((void**)&mha, g_mha);
    cudaGetSymbolAddress((void**)&kqh, g_kqh);
    cudaGetSymbolAddress((void**)&h1hi, g_h1hi);
    cudaGetSymbolAddress((void**)&h1lo, g_h1lo);
    cudaGetSymbolAddress((void**)&hnhi, g_hnhi);
    cudaGetSymbolAddress((void**)&hnlo, g_hnlo);
    cudaGetSymbolAddress((void**)&wkqhi, g_wkqhi);
    cudaGetSymbolAddress((void**)&wkqlo, g_wkqlo);
    cudaGetSymbolAddress((void**)&wrhi, g_wrhi);
    cudaGetSymbolAddress((void**)&wrlo, g_wrlo);
    cudaGetSymbolAddress((void**)&wmhi, g_wmhi);
    cudaGetSymbolAddress((void**)&wmlo, g_wmlo);
    cudaGetSymbolAddress((void**)&pjh,  g_pjh);

    cudaFuncSetAttribute(hgemm<false,false,false,false,true>, cudaFuncAttributeMaxDynamicSharedMemorySize, SMEMB);
    cudaFuncSetAttribute(hgemm<false,false,true,false,false>, cudaFuncAttributeMaxDynamicSharedMemorySize, SMEMB);
    cudaFuncSetAttribute(hgemm<true,true,true,true,false>,    cudaFuncAttributeMaxDynamicSharedMemorySize, SMEMB);
    cudaFuncSetAttribute(hgemm_h, cudaFuncAttributeMaxDynamicSharedMemorySize, H_SMEMB);

    prep_all<<<21120, 256>>>(Wk, Wq, Wres, mlpW, projW,
                             wkqhi, wkqlo, wrhi, wrlo, wmhi, wmlo, pjh);
    embed_kernel<<<MROWS, 128>>>(x, tok, pos, h1, h1hi, h1lo);

    dim3 gkq(MROWS / 128, 1024 / 64);            // 32 x 16 = 512 CTAs
    dim3 ge (MROWS / 128, Eq / 64);              // 32 x 8  = 256 CTAs
    for (int i = 0; i < NBq; i++) {
        const size_t wo   = (size_t)i * Eq * Eq;
        const size_t wokq = (size_t)i * 1024 * Eq;
        ln_split_kernel<false><<<MROWS, 128>>>(h1, ln1g + i * Eq, ln1b + i * Eq, hnhi, hnlo);
        hgemm<false,false,false,false,true><<<gkq, 256, SMEMB>>>(
            hnhi, hnlo, wkqhi + wokq, wkqlo + wokq, nullptr, nullptr,
            nullptr, nullptr, nullptr, kqh, 1024);
        flash_attn<<<dim3(Tq / 64, Bq * Hq), 128>>>(kqh, mha);
        hgemm<false,false,true,false,false><<<ge, 256, SMEMB>>>(
            h1hi, h1lo, wrhi + wo, wrlo + wo, nullptr, mha,
            h2, nullptr, nullptr, nullptr, Eq);
        ln_split_kernel<false><<<MROWS, 128>>>(h2, ln2g + i * Eq, ln2b + i * Eq, hnhi, hnlo);
        hgemm<true,true,true,true,false><<<ge, 256, SMEMB>>>(
            hnhi, hnlo, wmhi + wo, wmlo + wo, mlpb + i * Eq, h2,
            h1, h1hi, h1lo, nullptr, Eq);
    }

    // final LN emits fp16 splits (reusing hn buffers), projection in fp16x2
    ln_split_kernel<true><<<MROWS, 128>>>(h1, lnfg, lnfb, hnhi, hnlo);
    hgemm_h<<<dim3(MROWS / 128, VOC / 64), 256, H_SMEMB>>>(
        (const __half*)hnhi, (const __half*)hnlo, pjh, projb, out, VOC);
}